// round 14
// baseline (speedup 1.0000x reference)
#include <cuda_runtime.h>
#include <cuda_fp16.h>
#include <cstdint>

#define TPB  512
#define GRID 148

// ---- dynamic shared memory layout (bytes) ----
// h1 tiles: 128 rows x 128 fp16, padded row stride 272 B (conflict-free ldmatrix)
#define H1_STRIDE 272
#define H1A_OFF   0
#define H1B_OFF   34816                    // 128*272
#define PA_OFF    69632                    // 8 ngroups x 128 rows x f32    (4096)
#define PB_OFF    73728                    // 8 ngroups x 128 rows x float4 (16384)
#define W1_OFF    90112                    // packed layer-1 weights        (1536)
#define SMEM_TOTAL 91648

static __device__ __forceinline__ uint32_t smem_u32(const void* p) {
    uint32_t a;
    asm("{ .reg .u64 t; cvta.to.shared.u64 t, %1; cvt.u32.u64 %0, t; }" : "=r"(a) : "l"(p));
    return a;
}

static __device__ __forceinline__ uint32_t pack_f16(float a, float b) {
    __half2 t = __floats2half2_rn(a, b);
    return *reinterpret_cast<uint32_t*>(&t);
}

static __device__ __forceinline__ void ldsm_x4(uint32_t a[4], uint32_t addr) {
    asm volatile("ldmatrix.sync.aligned.m8n8.x4.shared.b16 {%0,%1,%2,%3}, [%4];"
                 : "=r"(a[0]), "=r"(a[1]), "=r"(a[2]), "=r"(a[3]) : "r"(addr));
}

// f16 accumulate: D,C are 2 regs (4 halves)
static __device__ __forceinline__ void mma16816_f16(uint32_t c[2], const uint32_t a[4],
                                                    uint32_t b0, uint32_t b1) {
    asm volatile(
        "mma.sync.aligned.m16n8k16.row.col.f16.f16.f16.f16 "
        "{%0,%1}, {%2,%3,%4,%5}, {%6,%7}, {%0,%1};"
        : "+r"(c[0]), "+r"(c[1])
        : "r"(a[0]), "r"(a[1]), "r"(a[2]), "r"(a[3]), "r"(b0), "r"(b1));
}

// f32 accumulate from f16 operands (for the layer-3 reduction mma)
static __device__ __forceinline__ void mma16816_f32(float c[4], const uint32_t a[4],
                                                    uint32_t b0, uint32_t b1) {
    asm volatile(
        "mma.sync.aligned.m16n8k16.row.col.f32.f16.f16.f32 "
        "{%0,%1,%2,%3}, {%4,%5,%6,%7}, {%8,%9}, {%0,%1,%2,%3};"
        : "+f"(c[0]), "+f"(c[1]), "+f"(c[2]), "+f"(c[3])
        : "r"(a[0]), "r"(a[1]), "r"(a[2]), "r"(a[3]), "r"(b0), "r"(b1));
}

// bias + relu applied in-place on a packed half2 accumulator register
static __device__ __forceinline__ uint32_t h2_bias_relu(uint32_t c, __half2 bias, __half2 z) {
    __half2 v = __hmax2(__hadd2(*reinterpret_cast<__half2*>(&c), bias), z);
    return *reinterpret_cast<uint32_t*>(&v);
}

__global__ void __launch_bounds__(TPB, 1) KroneNet_59485297049802_kernel(
    const float* __restrict__ x,
    const float* __restrict__ w1a, const float* __restrict__ w1b,
    const float* __restrict__ b1a, const float* __restrict__ b1b,
    const float* __restrict__ w2a, const float* __restrict__ w2b,
    const float* __restrict__ b2a, const float* __restrict__ b2b,
    const float* __restrict__ w3a, const float* __restrict__ w3b,
    const float* __restrict__ b3a, const float* __restrict__ b3b,
    float* __restrict__ out, int Bn)
{
    extern __shared__ __align__(16) char sm[];
    const uint32_t smb = smem_u32(sm);
    const int tid  = threadIdx.x;
    const int wid  = tid >> 5;
    const int lane = tid & 31;
    const int quad = lane >> 2;    // 0..7
    const int qlid = lane & 3;     // 0..3

    // stream split: s = wid&1 (0 = stream a, 1 = stream b); ngroup = wid>>1
    const int s  = wid & 1;
    const int ng = wid >> 1;       // 0..7, n-cols [16ng, 16ng+16)

    float*    pA  = reinterpret_cast<float*>(sm + PA_OFF);
    float4*   pB  = reinterpret_cast<float4*>(sm + PB_OFF);
    uint32_t* w1w = reinterpret_cast<uint32_t*>(sm + W1_OFF);

    // ---- one-time: pack layer-1 weights into SMEM (fp16x2, lane-major) ----
    // word index: ((s*2+g)*3 + which)*32 + lane; which: 0=w.x pair, 1=w.y pair, 2=bias pair
    if (tid < 128) {
        const int s_ = tid >> 6, g_ = (tid >> 5) & 1, l_ = tid & 31;
        const int k0 = g_ * 64 + 2 * l_;
        const float* w1s_ = s_ ? w1b : w1a;
        const float* b1s_ = s_ ? b1b : b1a;
        const int W = ((s_ * 2 + g_) * 3) * 32 + l_;
        w1w[W]      = pack_f16(w1s_[2 * k0],     w1s_[2 * k0 + 2]);
        w1w[W + 32] = pack_f16(w1s_[2 * k0 + 1], w1s_[2 * k0 + 3]);
        w1w[W + 64] = pack_f16(b1s_[k0],         b1s_[k0 + 1]);
    }

    const float* w2s = s ? w2b : w2a;

    // ---- persistent B fragments (this stream only, fp16): n = 16ng + 8j + quad ----
    uint32_t Bf[2][8][2];
    #pragma unroll
    for (int j = 0; j < 2; ++j) {
        const int n = 16 * ng + 8 * j + quad;
        #pragma unroll
        for (int kk = 0; kk < 8; ++kk) {
            const int k0 = 16 * kk + 2 * qlid;
            float2 lo = *reinterpret_cast<const float2*>(w2s + n * 128 + k0);
            float2 hi = *reinterpret_cast<const float2*>(w2s + n * 128 + k0 + 8);
            Bf[j][kk][0] = pack_f16(lo.x, lo.y);
            Bf[j][kk][1] = pack_f16(hi.x, hi.y);
        }
    }

    // ---- layer-2 bias for this thread's D cols (n = 16ng + 8j + 2qlid + {0,1}) ----
    const float* b2s = s ? b2b : b2a;
    __half2 bias2[2];
    #pragma unroll
    for (int j = 0; j < 2; ++j) {
        const int n = 16 * ng + 8 * j + 2 * qlid;
        bias2[j] = __floats2half2_rn(b2s[n], b2s[n + 1]);
    }

    // ---- w3 B-fragment for the layer-3 reduction mma (n8 x k16, col-major) ----
    uint32_t wf3[2];
    {
        float v0a = 0.f, v0b = 0.f, v1a = 0.f, v1b = 0.f;
        const int kg0 = 16 * ng + 2 * qlid;
        if (s == 0) {
            if (quad == 0) {
                v0a = w3a[kg0];     v0b = w3a[kg0 + 1];
                v1a = w3a[kg0 + 8]; v1b = w3a[kg0 + 9];
            }
        } else {
            if (quad < 3) {
                const float* w3r = w3b + quad * 128;
                v0a = w3r[kg0];     v0b = w3r[kg0 + 1];
                v1a = w3r[kg0 + 8]; v1b = w3r[kg0 + 9];
            }
        }
        wf3[0] = pack_f16(v0a, v0b);
        wf3[1] = pack_f16(v1a, v1b);
    }

    const float s_b3a = b3a[0];
    const float s_b3b0 = b3b[0], s_b3b1 = b3b[1], s_b3b2 = b3b[2];

    // ldmatrix per-lane source address (m8n8.x4 over 16 rows x 16 cols fp16)
    const uint32_t lrow  = (uint32_t)((lane & 7) + ((lane >> 3) & 1) * 8);
    const uint32_t lcolb = (uint32_t)(((lane >> 4) & 1) * 16);
    const uint32_t aS = smb + (s ? H1B_OFF : H1A_OFF) + lrow * H1_STRIDE + lcolb;

    const int ntiles = Bn >> 7;
    const float2* x2 = reinterpret_cast<const float2*>(x);
    const __half2 z2 = __floats2half2_rn(0.f, 0.f);

    __syncthreads();   // w1w visible

    for (int t = blockIdx.x; t < ntiles; t += gridDim.x) {
        // ---- layer 1: h1 = relu(W1 x + b1) -> fp16 SMEM (warp w: rows 8w..8w+7) ----
        {
            __half2 pw[2][2][3];   // short-lived: loaded from smem each tile
            #pragma unroll
            for (int ss = 0; ss < 2; ++ss)
                #pragma unroll
                for (int g = 0; g < 2; ++g)
                    #pragma unroll
                    for (int wh = 0; wh < 3; ++wh) {
                        uint32_t wv = w1w[((ss * 2 + g) * 3 + wh) * 32 + lane];
                        pw[ss][g][wh] = *reinterpret_cast<__half2*>(&wv);
                    }
            #pragma unroll
            for (int r = 0; r < 8; ++r) {
                const int row = wid * 8 + r;
                const int rg  = t * 128 + row;
                const float2 xa = x2[rg];
                const float2 xb = x2[Bn + rg];
                const __half2 xax = __half2half2(__float2half(xa.x));
                const __half2 xay = __half2half2(__float2half(xa.y));
                const __half2 xbx = __half2half2(__float2half(xb.x));
                const __half2 xby = __half2half2(__float2half(xb.y));
                char* rowa = sm + H1A_OFF + row * H1_STRIDE;
                char* rowb = sm + H1B_OFF + row * H1_STRIDE;
                #pragma unroll
                for (int g = 0; g < 2; ++g) {
                    __half2 ha = __hmax2(
                        __hfma2(xax, pw[0][g][0], __hfma2(xay, pw[0][g][1], pw[0][g][2])), z2);
                    __half2 hb = __hmax2(
                        __hfma2(xbx, pw[1][g][0], __hfma2(xby, pw[1][g][1], pw[1][g][2])), z2);
                    *reinterpret_cast<uint32_t*>(rowa + 128 * g + 4 * lane) =
                        *reinterpret_cast<uint32_t*>(&ha);
                    *reinterpret_cast<uint32_t*>(rowb + 128 * g + 4 * lane) =
                        *reinterpret_cast<uint32_t*>(&hb);
                }
            }
        }
        __syncthreads();

        // ---- layer 2: 2 m-tiles interleaved -> 4 independent HMMA chains ----
        #pragma unroll
        for (int ii = 0; ii < 4; ++ii) {
            const int i0 = 2 * ii, i1 = 2 * ii + 1;
            const uint32_t base0 = aS + (uint32_t)(i0 * 16 * H1_STRIDE);
            const uint32_t base1 = aS + (uint32_t)(i1 * 16 * H1_STRIDE);

            uint32_t c00[2] = {0u, 0u}, c01[2] = {0u, 0u};
            uint32_t c10[2] = {0u, 0u}, c11[2] = {0u, 0u};
            #pragma unroll
            for (int kk = 0; kk < 8; ++kk) {
                uint32_t af0[4], af1[4];
                ldsm_x4(af0, base0 + 32u * kk);
                ldsm_x4(af1, base1 + 32u * kk);
                mma16816_f16(c00, af0, Bf[0][kk][0], Bf[0][kk][1]);
                mma16816_f16(c01, af0, Bf[1][kk][0], Bf[1][kk][1]);
                mma16816_f16(c10, af1, Bf[0][kk][0], Bf[0][kk][1]);
                mma16816_f16(c11, af1, Bf[1][kk][0], Bf[1][kk][1]);
            }

            // ---- epilogue per m-tile: bias+relu in half2, layer-3 dot via HMMA ----
            #pragma unroll
            for (int m = 0; m < 2; ++m) {
                const uint32_t* cc0 = m ? c10 : c00;
                const uint32_t* cc1 = m ? c11 : c01;
                const int i = m ? i1 : i0;

                uint32_t h2f[4];
                h2f[0] = h2_bias_relu(cc0[0], bias2[0], z2);
                h2f[1] = h2_bias_relu(cc0[1], bias2[0], z2);
                h2f[2] = h2_bias_relu(cc1[0], bias2[1], z2);
                h2f[3] = h2_bias_relu(cc1[1], bias2[1], z2);

                float d[4] = {0.f, 0.f, 0.f, 0.f};
                mma16816_f32(d, h2f, wf3[0], wf3[1]);
                // d[0],d[1] = row quad,   cols {2qlid, 2qlid+1}
                // d[2],d[3] = row quad+8, cols {2qlid, 2qlid+1}

                if (s == 0) {
                    if (qlid == 0) {
                        pA[ng * 128 + 16 * i + quad]     = d[0];
                        pA[ng * 128 + 16 * i + quad + 8] = d[2];
                    }
                } else {
                    if (qlid < 2) {
                        float* dst0 = reinterpret_cast<float*>(&pB[ng * 128 + 16 * i + quad]) + 2 * qlid;
                        float* dst1 = reinterpret_cast<float*>(&pB[ng * 128 + 16 * i + quad + 8]) + 2 * qlid;
                        *reinterpret_cast<float2*>(dst0) = make_float2(d[0], d[1]);
                        *reinterpret_cast<float2*>(dst1) = make_float2(d[2], d[3]);
                    }
                }
            }
        }
        __syncthreads();

        // ---- final: combine 8 ngroup partials per stream, softmax, store ----
        if (tid < 128) {
            const int row = tid;
            float oa = s_b3a;
            float o0 = s_b3b0, o1 = s_b3b1, o2 = s_b3b2;
            #pragma unroll
            for (int g = 0; g < 8; ++g) {
                oa += pA[g * 128 + row];
                const float4 qb = pB[g * 128 + row];
                o0 += qb.x; o1 += qb.y; o2 += qb.z;
            }
            const float t0 = oa * o0, t1 = oa * o1, t2 = oa * o2;
            const float mx = fmaxf(t0, fmaxf(t1, t2));
            const float e0 = expf(t0 - mx), e1 = expf(t1 - mx), e2 = expf(t2 - mx);
            const float inv = 1.f / (e0 + e1 + e2);
            const int rg = t * 128 + row;
            out[rg * 3 + 0] = e0 * inv;
            out[rg * 3 + 1] = e1 * inv;
            out[rg * 3 + 2] = e2 * inv;
        }
        // next-tile pA/pB writes are separated from these reads by the
        // h1 __syncthreads at the top of the next iteration.
    }
}

extern "C" void kernel_launch(void* const* d_in, const int* in_sizes, int n_in,
                              void* d_out, int out_size) {
    const float* x   = (const float*)d_in[0];
    const float* w1a = (const float*)d_in[1];
    const float* w1b = (const float*)d_in[2];
    const float* b1a = (const float*)d_in[3];
    const float* b1b = (const float*)d_in[4];
    const float* w2a = (const float*)d_in[5];
    const float* w2b = (const float*)d_in[6];
    const float* b2a = (const float*)d_in[7];
    const float* b2b = (const float*)d_in[8];
    const float* w3a = (const float*)d_in[9];
    const float* w3b = (const float*)d_in[10];
    const float* b3a = (const float*)d_in[11];
    const float* b3b = (const float*)d_in[12];
    float* out = (float*)d_out;

    int Bn = in_sizes[0] / 4;   // x is (2, B, 2) fp32

    cudaFuncSetAttribute(KroneNet_59485297049802_kernel,
                         cudaFuncAttributeMaxDynamicSharedMemorySize, SMEM_TOTAL);
    KroneNet_59485297049802_kernel<<<GRID, TPB, SMEM_TOTAL>>>(
        x, w1a, w1b, b1a, b1b, w2a, w2b, b2a, b2b, w3a, w3b, b3a, b3b, out, Bn);
}

// round 15
// speedup vs baseline: 1.0753x; 1.0753x over previous
#include <cuda_runtime.h>
#include <cuda_fp16.h>
#include <cstdint>

#define TPB  512
#define GRID 148

// ---- dynamic shared memory layout (bytes) ----
// h1 tiles: 128 rows x 128 fp16, padded row stride 272 B (conflict-free ldmatrix)
#define H1_STRIDE 272
#define H1A_OFF   0
#define H1B_OFF   34816                    // 128*272
#define PA_OFF    69632                    // 4 slots x 128 rows x f32    (2048)
#define PB_OFF    71680                    // 4 slots x 128 rows x float4 (8192)
#define W1_OFF    79872                    // packed layer-1 weights      (1536)
#define SMEM_TOTAL 81408

static __device__ __forceinline__ uint32_t smem_u32(const void* p) {
    uint32_t a;
    asm("{ .reg .u64 t; cvta.to.shared.u64 t, %1; cvt.u32.u64 %0, t; }" : "=r"(a) : "l"(p));
    return a;
}

static __device__ __forceinline__ uint32_t pack_f16(float a, float b) {
    __half2 t = __floats2half2_rn(a, b);
    return *reinterpret_cast<uint32_t*>(&t);
}

static __device__ __forceinline__ void ldsm_x4(uint32_t a[4], uint32_t addr) {
    asm volatile("ldmatrix.sync.aligned.m8n8.x4.shared.b16 {%0,%1,%2,%3}, [%4];"
                 : "=r"(a[0]), "=r"(a[1]), "=r"(a[2]), "=r"(a[3]) : "r"(addr));
}

// f16 accumulate: D,C are 2 regs (4 halves)
static __device__ __forceinline__ void mma16816_f16(uint32_t c[2], const uint32_t a[4],
                                                    uint32_t b0, uint32_t b1) {
    asm volatile(
        "mma.sync.aligned.m16n8k16.row.col.f16.f16.f16.f16 "
        "{%0,%1}, {%2,%3,%4,%5}, {%6,%7}, {%0,%1};"
        : "+r"(c[0]), "+r"(c[1])
        : "r"(a[0]), "r"(a[1]), "r"(a[2]), "r"(a[3]), "r"(b0), "r"(b1));
}

// f32 accumulate from f16 operands (layer-3 reduction mma)
static __device__ __forceinline__ void mma16816_f32(float c[4], const uint32_t a[4],
                                                    uint32_t b0, uint32_t b1) {
    asm volatile(
        "mma.sync.aligned.m16n8k16.row.col.f32.f16.f16.f32 "
        "{%0,%1,%2,%3}, {%4,%5,%6,%7}, {%8,%9}, {%0,%1,%2,%3};"
        : "+f"(c[0]), "+f"(c[1]), "+f"(c[2]), "+f"(c[3])
        : "r"(a[0]), "r"(a[1]), "r"(a[2]), "r"(a[3]), "r"(b0), "r"(b1));
}

// bias + relu applied in-place on a packed half2 accumulator register
static __device__ __forceinline__ uint32_t h2_bias_relu(uint32_t c, __half2 bias, __half2 z) {
    __half2 v = __hmax2(__hadd2(*reinterpret_cast<__half2*>(&c), bias), z);
    return *reinterpret_cast<uint32_t*>(&v);
}

__global__ void __launch_bounds__(TPB, 1) KroneNet_59485297049802_kernel(
    const float* __restrict__ x,
    const float* __restrict__ w1a, const float* __restrict__ w1b,
    const float* __restrict__ b1a, const float* __restrict__ b1b,
    const float* __restrict__ w2a, const float* __restrict__ w2b,
    const float* __restrict__ b2a, const float* __restrict__ b2b,
    const float* __restrict__ w3a, const float* __restrict__ w3b,
    const float* __restrict__ b3a, const float* __restrict__ b3b,
    float* __restrict__ out, int Bn)
{
    extern __shared__ __align__(16) char sm[];
    const uint32_t smb = smem_u32(sm);
    const int tid  = threadIdx.x;
    const int wid  = tid >> 5;
    const int lane = tid & 31;
    const int quad = lane >> 2;    // 0..7
    const int qlid = lane & 3;     // 0..3

    // warp grid: s = wid&1 (stream); per stream 8 warps = 2 m-groups x 4 n-groups
    const int s  = wid & 1;
    const int wp = wid >> 1;       // 0..7
    const int mg = wp & 1;         // m-tiles [4mg, 4mg+4)
    const int ng = wp >> 1;        // 0..3, n-cols [32ng, 32ng+32)

    float*    pA  = reinterpret_cast<float*>(sm + PA_OFF);
    float4*   pB  = reinterpret_cast<float4*>(sm + PB_OFF);
    uint32_t* w1w = reinterpret_cast<uint32_t*>(sm + W1_OFF);

    // ---- one-time: pack layer-1 weights into SMEM (fp16x2, lane-major) ----
    if (tid < 128) {
        const int s_ = tid >> 6, g_ = (tid >> 5) & 1, l_ = tid & 31;
        const int k0 = g_ * 64 + 2 * l_;
        const float* w1s_ = s_ ? w1b : w1a;
        const float* b1s_ = s_ ? b1b : b1a;
        const int W = ((s_ * 2 + g_) * 3) * 32 + l_;
        w1w[W]      = pack_f16(w1s_[2 * k0],     w1s_[2 * k0 + 2]);
        w1w[W + 32] = pack_f16(w1s_[2 * k0 + 1], w1s_[2 * k0 + 3]);
        w1w[W + 64] = pack_f16(b1s_[k0],         b1s_[k0 + 1]);
    }

    const float* w2s = s ? w2b : w2a;

    // ---- persistent B fragments (fp16): n = 32ng + 8j + quad, j in 0..3 ----
    uint32_t Bf[4][8][2];
    #pragma unroll
    for (int j = 0; j < 4; ++j) {
        const int n = 32 * ng + 8 * j + quad;
        #pragma unroll
        for (int kk = 0; kk < 8; ++kk) {
            const int k0 = 16 * kk + 2 * qlid;
            float2 lo = *reinterpret_cast<const float2*>(w2s + n * 128 + k0);
            float2 hi = *reinterpret_cast<const float2*>(w2s + n * 128 + k0 + 8);
            Bf[j][kk][0] = pack_f16(lo.x, lo.y);
            Bf[j][kk][1] = pack_f16(hi.x, hi.y);
        }
    }

    // ---- layer-2 bias for this thread's D cols (n = 32ng + 8j + 2qlid + {0,1}) ----
    const float* b2s = s ? b2b : b2a;
    __half2 bias2[4];
    #pragma unroll
    for (int j = 0; j < 4; ++j) {
        const int n = 32 * ng + 8 * j + 2 * qlid;
        bias2[j] = __floats2half2_rn(b2s[n], b2s[n + 1]);
    }

    // ---- w3 B-fragments for the 2 layer-3 reduction mmas (k-slice p: 16 cols) ----
    // k-global = 32ng + 16p + 2qlid + {0,1,8,9}; n-row of frag = quad = channel
    uint32_t wf3[2][2];
    #pragma unroll
    for (int p = 0; p < 2; ++p) {
        float v0a = 0.f, v0b = 0.f, v1a = 0.f, v1b = 0.f;
        const int kg0 = 32 * ng + 16 * p + 2 * qlid;
        if (s == 0) {
            if (quad == 0) {
                v0a = w3a[kg0];     v0b = w3a[kg0 + 1];
                v1a = w3a[kg0 + 8]; v1b = w3a[kg0 + 9];
            }
        } else {
            if (quad < 3) {
                const float* w3r = w3b + quad * 128;
                v0a = w3r[kg0];     v0b = w3r[kg0 + 1];
                v1a = w3r[kg0 + 8]; v1b = w3r[kg0 + 9];
            }
        }
        wf3[p][0] = pack_f16(v0a, v0b);
        wf3[p][1] = pack_f16(v1a, v1b);
    }

    const float s_b3a = b3a[0];
    const float s_b3b0 = b3b[0], s_b3b1 = b3b[1], s_b3b2 = b3b[2];

    // ldmatrix per-lane source address (m8n8.x4 over 16 rows x 16 cols fp16)
    const uint32_t lrow  = (uint32_t)((lane & 7) + ((lane >> 3) & 1) * 8);
    const uint32_t lcolb = (uint32_t)(((lane >> 4) & 1) * 16);
    const uint32_t aS = smb + (s ? H1B_OFF : H1A_OFF) + lrow * H1_STRIDE + lcolb;

    const int ntiles = Bn >> 7;
    const float2* x2 = reinterpret_cast<const float2*>(x);
    const __half2 z2 = __floats2half2_rn(0.f, 0.f);

    __syncthreads();   // w1w visible

    for (int t = blockIdx.x; t < ntiles; t += gridDim.x) {
        // ---- layer 1: h1 = relu(W1 x + b1) -> fp16 SMEM (warp w: rows 8w..8w+7) ----
        {
            __half2 pw[2][2][3];   // short-lived: loaded from smem each tile
            #pragma unroll
            for (int ss = 0; ss < 2; ++ss)
                #pragma unroll
                for (int g = 0; g < 2; ++g)
                    #pragma unroll
                    for (int wh = 0; wh < 3; ++wh) {
                        uint32_t wv = w1w[((ss * 2 + g) * 3 + wh) * 32 + lane];
                        pw[ss][g][wh] = *reinterpret_cast<__half2*>(&wv);
                    }
            #pragma unroll
            for (int r = 0; r < 8; ++r) {
                const int row = wid * 8 + r;
                const int rg  = t * 128 + row;
                const float2 xa = x2[rg];
                const float2 xb = x2[Bn + rg];
                const __half2 xax = __half2half2(__float2half(xa.x));
                const __half2 xay = __half2half2(__float2half(xa.y));
                const __half2 xbx = __half2half2(__float2half(xb.x));
                const __half2 xby = __half2half2(__float2half(xb.y));
                char* rowa = sm + H1A_OFF + row * H1_STRIDE;
                char* rowb = sm + H1B_OFF + row * H1_STRIDE;
                #pragma unroll
                for (int g = 0; g < 2; ++g) {
                    __half2 ha = __hmax2(
                        __hfma2(xax, pw[0][g][0], __hfma2(xay, pw[0][g][1], pw[0][g][2])), z2);
                    __half2 hb = __hmax2(
                        __hfma2(xbx, pw[1][g][0], __hfma2(xby, pw[1][g][1], pw[1][g][2])), z2);
                    *reinterpret_cast<uint32_t*>(rowa + 128 * g + 4 * lane) =
                        *reinterpret_cast<uint32_t*>(&ha);
                    *reinterpret_cast<uint32_t*>(rowb + 128 * g + 4 * lane) =
                        *reinterpret_cast<uint32_t*>(&hb);
                }
            }
        }
        __syncthreads();

        // ---- layer 2: 4 m-tiles x 32 n-cols per warp (1 ldsm feeds 4 HMMA) ----
        #pragma unroll
        for (int ii = 0; ii < 4; ++ii) {
            const int i = 4 * mg + ii;
            const uint32_t ibase = aS + (uint32_t)(i * 16 * H1_STRIDE);

            uint32_t c[4][2];
            #pragma unroll
            for (int j = 0; j < 4; ++j) { c[j][0] = 0u; c[j][1] = 0u; }

            #pragma unroll
            for (int kk = 0; kk < 8; ++kk) {
                uint32_t af[4];
                ldsm_x4(af, ibase + 32u * kk);
                #pragma unroll
                for (int j = 0; j < 4; ++j)
                    mma16816_f16(c[j], af, Bf[j][kk][0], Bf[j][kk][1]);
            }

            // ---- epilogue: bias+relu in half2, layer-3 dot via 2 reduction HMMA ----
            float d[4] = {0.f, 0.f, 0.f, 0.f};
            #pragma unroll
            for (int p = 0; p < 2; ++p) {
                uint32_t h2f[4];
                h2f[0] = h2_bias_relu(c[2 * p][0],     bias2[2 * p],     z2);
                h2f[1] = h2_bias_relu(c[2 * p][1],     bias2[2 * p],     z2);
                h2f[2] = h2_bias_relu(c[2 * p + 1][0], bias2[2 * p + 1], z2);
                h2f[3] = h2_bias_relu(c[2 * p + 1][1], bias2[2 * p + 1], z2);
                mma16816_f32(d, h2f, wf3[p][0], wf3[p][1]);
            }
            // d[0],d[1] = row quad,   cols {2qlid, 2qlid+1}
            // d[2],d[3] = row quad+8, cols {2qlid, 2qlid+1}

            if (s == 0) {
                if (qlid == 0) {
                    pA[ng * 128 + 16 * i + quad]     = d[0];
                    pA[ng * 128 + 16 * i + quad + 8] = d[2];
                }
            } else {
                if (qlid < 2) {
                    float* dst0 = reinterpret_cast<float*>(&pB[ng * 128 + 16 * i + quad]) + 2 * qlid;
                    float* dst1 = reinterpret_cast<float*>(&pB[ng * 128 + 16 * i + quad + 8]) + 2 * qlid;
                    *reinterpret_cast<float2*>(dst0) = make_float2(d[0], d[1]);
                    *reinterpret_cast<float2*>(dst1) = make_float2(d[2], d[3]);
                }
            }
        }
        __syncthreads();

        // ---- final: combine 4 n-group partials per stream, softmax, store ----
        if (tid < 128) {
            const int row = tid;
            float oa = s_b3a;
            float o0 = s_b3b0, o1 = s_b3b1, o2 = s_b3b2;
            #pragma unroll
            for (int g = 0; g < 4; ++g) {
                oa += pA[g * 128 + row];
                const float4 qb = pB[g * 128 + row];
                o0 += qb.x; o1 += qb.y; o2 += qb.z;
            }
            const float t0 = oa * o0, t1 = oa * o1, t2 = oa * o2;
            const float mx = fmaxf(t0, fmaxf(t1, t2));
            const float e0 = expf(t0 - mx), e1 = expf(t1 - mx), e2 = expf(t2 - mx);
            const float inv = 1.f / (e0 + e1 + e2);
            const int rg = t * 128 + row;
            out[rg * 3 + 0] = e0 * inv;
            out[rg * 3 + 1] = e1 * inv;
            out[rg * 3 + 2] = e2 * inv;
        }
        // next-tile pA/pB writes are separated from these reads by the
        // h1 __syncthreads at the top of the next iteration.
    }
}

extern "C" void kernel_launch(void* const* d_in, const int* in_sizes, int n_in,
                              void* d_out, int out_size) {
    const float* x   = (const float*)d_in[0];
    const float* w1a = (const float*)d_in[1];
    const float* w1b = (const float*)d_in[2];
    const float* b1a = (const float*)d_in[3];
    const float* b1b = (const float*)d_in[4];
    const float* w2a = (const float*)d_in[5];
    const float* w2b = (const float*)d_in[6];
    const float* b2a = (const float*)d_in[7];
    const float* b2b = (const float*)d_in[8];
    const float* w3a = (const float*)d_in[9];
    const float* w3b = (const float*)d_in[10];
    const float* b3a = (const float*)d_in[11];
    const float* b3b = (const float*)d_in[12];
    float* out = (float*)d_out;

    int Bn = in_sizes[0] / 4;   // x is (2, B, 2) fp32

    cudaFuncSetAttribute(KroneNet_59485297049802_kernel,
                         cudaFuncAttributeMaxDynamicSharedMemorySize, SMEM_TOTAL);
    KroneNet_59485297049802_kernel<<<GRID, TPB, SMEM_TOTAL>>>(
        x, w1a, w1b, b1a, b1b, w2a, w2b, b2a, b2b, w3a, w3b, b3a, b3b, out, Bn);
}

// round 16
// speedup vs baseline: 1.0825x; 1.0067x over previous
#include <cuda_runtime.h>
#include <cuda_fp16.h>
#include <cstdint>

#define TPB  256
#define GRID 296

// ---- dynamic shared memory layout (bytes) ----
// h1 tiles: 128 rows x 128 fp16, padded row stride 272 B (conflict-free ldmatrix)
#define H1_STRIDE 272
#define H1A_OFF   0
#define H1B_OFF   34816                    // 128*272
#define PA_OFF    69632                    // 4 slots x 128 rows x f32    (2048)
#define PB_OFF    71680                    // 4 slots x 128 rows x float4 (8192)
#define W1_OFF    79872                    // packed layer-1 weights      (1536)
#define SMEM_TOTAL 81408

static __device__ __forceinline__ uint32_t smem_u32(const void* p) {
    uint32_t a;
    asm("{ .reg .u64 t; cvta.to.shared.u64 t, %1; cvt.u32.u64 %0, t; }" : "=r"(a) : "l"(p));
    return a;
}

static __device__ __forceinline__ uint32_t pack_f16(float a, float b) {
    __half2 t = __floats2half2_rn(a, b);
    return *reinterpret_cast<uint32_t*>(&t);
}

static __device__ __forceinline__ void ldsm_x4(uint32_t a[4], uint32_t addr) {
    asm volatile("ldmatrix.sync.aligned.m8n8.x4.shared.b16 {%0,%1,%2,%3}, [%4];"
                 : "=r"(a[0]), "=r"(a[1]), "=r"(a[2]), "=r"(a[3]) : "r"(addr));
}

// f16 accumulate: D,C are 2 regs (4 halves)
static __device__ __forceinline__ void mma16816_f16(uint32_t c[2], const uint32_t a[4],
                                                    uint32_t b0, uint32_t b1) {
    asm volatile(
        "mma.sync.aligned.m16n8k16.row.col.f16.f16.f16.f16 "
        "{%0,%1}, {%2,%3,%4,%5}, {%6,%7}, {%0,%1};"
        : "+r"(c[0]), "+r"(c[1])
        : "r"(a[0]), "r"(a[1]), "r"(a[2]), "r"(a[3]), "r"(b0), "r"(b1));
}

// f32 accumulate from f16 operands (layer-3 reduction mma)
static __device__ __forceinline__ void mma16816_f32(float c[4], const uint32_t a[4],
                                                    uint32_t b0, uint32_t b1) {
    asm volatile(
        "mma.sync.aligned.m16n8k16.row.col.f32.f16.f16.f32 "
        "{%0,%1,%2,%3}, {%4,%5,%6,%7}, {%8,%9}, {%0,%1,%2,%3};"
        : "+f"(c[0]), "+f"(c[1]), "+f"(c[2]), "+f"(c[3])
        : "r"(a[0]), "r"(a[1]), "r"(a[2]), "r"(a[3]), "r"(b0), "r"(b1));
}

// bias + relu applied in-place on a packed half2 accumulator register
static __device__ __forceinline__ uint32_t h2_bias_relu(uint32_t c, __half2 bias, __half2 z) {
    __half2 v = __hmax2(__hadd2(*reinterpret_cast<__half2*>(&c), bias), z);
    return *reinterpret_cast<uint32_t*>(&v);
}

__global__ void __launch_bounds__(TPB, 2) KroneNet_59485297049802_kernel(
    const float* __restrict__ x,
    const float* __restrict__ w1a, const float* __restrict__ w1b,
    const float* __restrict__ b1a, const float* __restrict__ b1b,
    const float* __restrict__ w2a, const float* __restrict__ w2b,
    const float* __restrict__ b2a, const float* __restrict__ b2b,
    const float* __restrict__ w3a, const float* __restrict__ w3b,
    const float* __restrict__ b3a, const float* __restrict__ b3b,
    float* __restrict__ out, int Bn)
{
    extern __shared__ __align__(16) char sm[];
    const uint32_t smb = smem_u32(sm);
    const int tid  = threadIdx.x;
    const int wid  = tid >> 5;     // 0..7
    const int lane = tid & 31;
    const int quad = lane >> 2;    // 0..7
    const int qlid = lane & 3;     // 0..3

    // warp grid: s = wid&1 (stream); ng = wid>>1 (0..3, n-cols [32ng, 32ng+32))
    // each warp covers ALL 8 m-tiles of its stream
    const int s  = wid & 1;
    const int ng = wid >> 1;

    float*    pA  = reinterpret_cast<float*>(sm + PA_OFF);
    float4*   pB  = reinterpret_cast<float4*>(sm + PB_OFF);
    uint32_t* w1w = reinterpret_cast<uint32_t*>(sm + W1_OFF);

    // ---- one-time: pack layer-1 weights into SMEM (fp16x2, lane-major) ----
    if (tid < 128) {
        const int s_ = tid >> 6, g_ = (tid >> 5) & 1, l_ = tid & 31;
        const int k0 = g_ * 64 + 2 * l_;
        const float* w1s_ = s_ ? w1b : w1a;
        const float* b1s_ = s_ ? b1b : b1a;
        const int W = ((s_ * 2 + g_) * 3) * 32 + l_;
        w1w[W]      = pack_f16(w1s_[2 * k0],     w1s_[2 * k0 + 2]);
        w1w[W + 32] = pack_f16(w1s_[2 * k0 + 1], w1s_[2 * k0 + 3]);
        w1w[W + 64] = pack_f16(b1s_[k0],         b1s_[k0 + 1]);
    }

    const float* w2s = s ? w2b : w2a;

    // ---- persistent B fragments (fp16): n = 32ng + 8j + quad, j in 0..3 ----
    uint32_t Bf[4][8][2];
    #pragma unroll
    for (int j = 0; j < 4; ++j) {
        const int n = 32 * ng + 8 * j + quad;
        #pragma unroll
        for (int kk = 0; kk < 8; ++kk) {
            const int k0 = 16 * kk + 2 * qlid;
            float2 lo = *reinterpret_cast<const float2*>(w2s + n * 128 + k0);
            float2 hi = *reinterpret_cast<const float2*>(w2s + n * 128 + k0 + 8);
            Bf[j][kk][0] = pack_f16(lo.x, lo.y);
            Bf[j][kk][1] = pack_f16(hi.x, hi.y);
        }
    }

    // ---- layer-2 bias for this thread's D cols (n = 32ng + 8j + 2qlid + {0,1}) ----
    const float* b2s = s ? b2b : b2a;
    __half2 bias2[4];
    #pragma unroll
    for (int j = 0; j < 4; ++j) {
        const int n = 32 * ng + 8 * j + 2 * qlid;
        bias2[j] = __floats2half2_rn(b2s[n], b2s[n + 1]);
    }

    // ---- w3 B-fragments for the 2 layer-3 reduction mmas (k-slice p: 16 cols) ----
    uint32_t wf3[2][2];
    #pragma unroll
    for (int p = 0; p < 2; ++p) {
        float v0a = 0.f, v0b = 0.f, v1a = 0.f, v1b = 0.f;
        const int kg0 = 32 * ng + 16 * p + 2 * qlid;
        if (s == 0) {
            if (quad == 0) {
                v0a = w3a[kg0];     v0b = w3a[kg0 + 1];
                v1a = w3a[kg0 + 8]; v1b = w3a[kg0 + 9];
            }
        } else {
            if (quad < 3) {
                const float* w3r = w3b + quad * 128;
                v0a = w3r[kg0];     v0b = w3r[kg0 + 1];
                v1a = w3r[kg0 + 8]; v1b = w3r[kg0 + 9];
            }
        }
        wf3[p][0] = pack_f16(v0a, v0b);
        wf3[p][1] = pack_f16(v1a, v1b);
    }

    const float s_b3a = b3a[0];
    const float s_b3b0 = b3b[0], s_b3b1 = b3b[1], s_b3b2 = b3b[2];

    // ldmatrix per-lane source address (m8n8.x4 over 16 rows x 16 cols fp16)
    const uint32_t lrow  = (uint32_t)((lane & 7) + ((lane >> 3) & 1) * 8);
    const uint32_t lcolb = (uint32_t)(((lane >> 4) & 1) * 16);
    const uint32_t aS = smb + (s ? H1B_OFF : H1A_OFF) + lrow * H1_STRIDE + lcolb;

    const int ntiles = Bn >> 7;
    const float2* x2 = reinterpret_cast<const float2*>(x);
    const __half2 z2 = __floats2half2_rn(0.f, 0.f);

    __syncthreads();   // w1w visible

    for (int t = blockIdx.x; t < ntiles; t += gridDim.x) {
        // ---- layer 1: h1 = relu(W1 x + b1) -> fp16 SMEM (warp w: rows 16w..16w+15) ----
        {
            __half2 pw[2][2][3];   // short-lived: loaded from smem each tile
            #pragma unroll
            for (int ss = 0; ss < 2; ++ss)
                #pragma unroll
                for (int g = 0; g < 2; ++g)
                    #pragma unroll
                    for (int wh = 0; wh < 3; ++wh) {
                        uint32_t wv = w1w[((ss * 2 + g) * 3 + wh) * 32 + lane];
                        pw[ss][g][wh] = *reinterpret_cast<__half2*>(&wv);
                    }
            #pragma unroll 4
            for (int r = 0; r < 16; ++r) {
                const int row = wid * 16 + r;
                const int rg  = t * 128 + row;
                const float2 xa = x2[rg];
                const float2 xb = x2[Bn + rg];
                const __half2 xax = __half2half2(__float2half(xa.x));
                const __half2 xay = __half2half2(__float2half(xa.y));
                const __half2 xbx = __half2half2(__float2half(xb.x));
                const __half2 xby = __half2half2(__float2half(xb.y));
                char* rowa = sm + H1A_OFF + row * H1_STRIDE;
                char* rowb = sm + H1B_OFF + row * H1_STRIDE;
                #pragma unroll
                for (int g = 0; g < 2; ++g) {
                    __half2 ha = __hmax2(
                        __hfma2(xax, pw[0][g][0], __hfma2(xay, pw[0][g][1], pw[0][g][2])), z2);
                    __half2 hb = __hmax2(
                        __hfma2(xbx, pw[1][g][0], __hfma2(xby, pw[1][g][1], pw[1][g][2])), z2);
                    *reinterpret_cast<uint32_t*>(rowa + 128 * g + 4 * lane) =
                        *reinterpret_cast<uint32_t*>(&ha);
                    *reinterpret_cast<uint32_t*>(rowb + 128 * g + 4 * lane) =
                        *reinterpret_cast<uint32_t*>(&hb);
                }
            }
        }
        __syncthreads();

        // ---- layer 2: 8 m-tiles x 32 n-cols per warp (1 ldsm feeds 4 HMMA) ----
        #pragma unroll
        for (int i = 0; i < 8; ++i) {
            const uint32_t ibase = aS + (uint32_t)(i * 16 * H1_STRIDE);

            uint32_t c[4][2];
            #pragma unroll
            for (int j = 0; j < 4; ++j) { c[j][0] = 0u; c[j][1] = 0u; }

            #pragma unroll
            for (int kk = 0; kk < 8; ++kk) {
                uint32_t af[4];
                ldsm_x4(af, ibase + 32u * kk);
                #pragma unroll
                for (int j = 0; j < 4; ++j)
                    mma16816_f16(c[j], af, Bf[j][kk][0], Bf[j][kk][1]);
            }

            // ---- epilogue: bias+relu in half2, layer-3 dot via 2 reduction HMMA ----
            float d[4] = {0.f, 0.f, 0.f, 0.f};
            #pragma unroll
            for (int p = 0; p < 2; ++p) {
                uint32_t h2f[4];
                h2f[0] = h2_bias_relu(c[2 * p][0],     bias2[2 * p],     z2);
                h2f[1] = h2_bias_relu(c[2 * p][1],     bias2[2 * p],     z2);
                h2f[2] = h2_bias_relu(c[2 * p + 1][0], bias2[2 * p + 1], z2);
                h2f[3] = h2_bias_relu(c[2 * p + 1][1], bias2[2 * p + 1], z2);
                mma16816_f32(d, h2f, wf3[p][0], wf3[p][1]);
            }
            // d[0],d[1] = row quad,   cols {2qlid, 2qlid+1}
            // d[2],d[3] = row quad+8, cols {2qlid, 2qlid+1}

            if (s == 0) {
                if (qlid == 0) {
                    pA[ng * 128 + 16 * i + quad]     = d[0];
                    pA[ng * 128 + 16 * i + quad + 8] = d[2];
                }
            } else {
                if (qlid < 2) {
                    float* dst0 = reinterpret_cast<float*>(&pB[ng * 128 + 16 * i + quad]) + 2 * qlid;
                    float* dst1 = reinterpret_cast<float*>(&pB[ng * 128 + 16 * i + quad + 8]) + 2 * qlid;
                    *reinterpret_cast<float2*>(dst0) = make_float2(d[0], d[1]);
                    *reinterpret_cast<float2*>(dst1) = make_float2(d[2], d[3]);
                }
            }
        }
        __syncthreads();

        // ---- final: combine 4 n-group partials per stream, softmax, store ----
        if (tid < 128) {
            const int row = tid;
            float oa = s_b3a;
            float o0 = s_b3b0, o1 = s_b3b1, o2 = s_b3b2;
            #pragma unroll
            for (int g = 0; g < 4; ++g) {
                oa += pA[g * 128 + row];
                const float4 qb = pB[g * 128 + row];
                o0 += qb.x; o1 += qb.y; o2 += qb.z;
            }
            const float t0 = oa * o0, t1 = oa * o1, t2 = oa * o2;
            const float mx = fmaxf(t0, fmaxf(t1, t2));
            const float e0 = expf(t0 - mx), e1 = expf(t1 - mx), e2 = expf(t2 - mx);
            const float inv = 1.f / (e0 + e1 + e2);
            const int rg = t * 128 + row;
            out[rg * 3 + 0] = e0 * inv;
            out[rg * 3 + 1] = e1 * inv;
            out[rg * 3 + 2] = e2 * inv;
        }
        // next-tile pA/pB writes are separated from these reads by the
        // h1 __syncthreads at the top of the next iteration.
    }
}

extern "C" void kernel_launch(void* const* d_in, const int* in_sizes, int n_in,
                              void* d_out, int out_size) {
    const float* x   = (const float*)d_in[0];
    const float* w1a = (const float*)d_in[1];
    const float* w1b = (const float*)d_in[2];
    const float* b1a = (const float*)d_in[3];
    const float* b1b = (const float*)d_in[4];
    const float* w2a = (const float*)d_in[5];
    const float* w2b = (const float*)d_in[6];
    const float* b2a = (const float*)d_in[7];
    const float* b2b = (const float*)d_in[8];
    const float* w3a = (const float*)d_in[9];
    const float* w3b = (const float*)d_in[10];
    const float* b3a = (const float*)d_in[11];
    const float* b3b = (const float*)d_in[12];
    float* out = (float*)d_out;

    int Bn = in_sizes[0] / 4;   // x is (2, B, 2) fp32

    cudaFuncSetAttribute(KroneNet_59485297049802_kernel,
                         cudaFuncAttributeMaxDynamicSharedMemorySize, SMEM_TOTAL);
    KroneNet_59485297049802_kernel<<<GRID, TPB, SMEM_TOTAL>>>(
        x, w1a, w1b, b1a, b1b, w2a, w2b, b2a, b2b, w3a, w3b, b3a, b3b, out, Bn);
}

// round 17
// speedup vs baseline: 1.0867x; 1.0039x over previous
#include <cuda_runtime.h>
#include <cuda_fp16.h>
#include <cstdint>

#define TPB  256
#define GRID 296

// ---- dynamic shared memory layout (bytes) ----
// h1 tiles: 128 rows x 128 fp16, padded row stride 272 B (conflict-free ldmatrix)
#define H1_STRIDE 272
#define H1A_OFF   0
#define H1B_OFF   34816                    // 128*272
#define PA_OFF    69632                    // 4 slots x 128 rows x f32    (2048)
#define PB_OFF    71680                    // 4 slots x 128 rows x float4 (8192)
#define W1_OFF    79872                    // packed layer-1 weights      (1536)
#define XS_OFF    81408                    // x stage: 256 float2         (2048)
#define SMEM_TOTAL 83456

static __device__ __forceinline__ uint32_t smem_u32(const void* p) {
    uint32_t a;
    asm("{ .reg .u64 t; cvta.to.shared.u64 t, %1; cvt.u32.u64 %0, t; }" : "=r"(a) : "l"(p));
    return a;
}

static __device__ __forceinline__ uint32_t pack_f16(float a, float b) {
    __half2 t = __floats2half2_rn(a, b);
    return *reinterpret_cast<uint32_t*>(&t);
}

static __device__ __forceinline__ void ldsm_x4(uint32_t a[4], uint32_t addr) {
    asm volatile("ldmatrix.sync.aligned.m8n8.x4.shared.b16 {%0,%1,%2,%3}, [%4];"
                 : "=r"(a[0]), "=r"(a[1]), "=r"(a[2]), "=r"(a[3]) : "r"(addr));
}

// f16 accumulate: D,C are 2 regs (4 halves)
static __device__ __forceinline__ void mma16816_f16(uint32_t c[2], const uint32_t a[4],
                                                    uint32_t b0, uint32_t b1) {
    asm volatile(
        "mma.sync.aligned.m16n8k16.row.col.f16.f16.f16.f16 "
        "{%0,%1}, {%2,%3,%4,%5}, {%6,%7}, {%0,%1};"
        : "+r"(c[0]), "+r"(c[1])
        : "r"(a[0]), "r"(a[1]), "r"(a[2]), "r"(a[3]), "r"(b0), "r"(b1));
}

// f32 accumulate from f16 operands (layer-3 reduction mma)
static __device__ __forceinline__ void mma16816_f32(float c[4], const uint32_t a[4],
                                                    uint32_t b0, uint32_t b1) {
    asm volatile(
        "mma.sync.aligned.m16n8k16.row.col.f32.f16.f16.f32 "
        "{%0,%1,%2,%3}, {%4,%5,%6,%7}, {%8,%9}, {%0,%1,%2,%3};"
        : "+f"(c[0]), "+f"(c[1]), "+f"(c[2]), "+f"(c[3])
        : "r"(a[0]), "r"(a[1]), "r"(a[2]), "r"(a[3]), "r"(b0), "r"(b1));
}

// bias + relu applied in-place on a packed half2 accumulator register
static __device__ __forceinline__ uint32_t h2_bias_relu(uint32_t c, __half2 bias, __half2 z) {
    __half2 v = __hmax2(__hadd2(*reinterpret_cast<__half2*>(&c), bias), z);
    return *reinterpret_cast<uint32_t*>(&v);
}

__global__ void __launch_bounds__(TPB, 2) KroneNet_59485297049802_kernel(
    const float* __restrict__ x,
    const float* __restrict__ w1a, const float* __restrict__ w1b,
    const float* __restrict__ b1a, const float* __restrict__ b1b,
    const float* __restrict__ w2a, const float* __restrict__ w2b,
    const float* __restrict__ b2a, const float* __restrict__ b2b,
    const float* __restrict__ w3a, const float* __restrict__ w3b,
    const float* __restrict__ b3a, const float* __restrict__ b3b,
    float* __restrict__ out, int Bn)
{
    extern __shared__ __align__(16) char sm[];
    const uint32_t smb = smem_u32(sm);
    const int tid  = threadIdx.x;
    const int wid  = tid >> 5;     // 0..7
    const int lane = tid & 31;
    const int quad = lane >> 2;    // 0..7
    const int qlid = lane & 3;     // 0..3

    // phase stagger: 2nd CTA on each SM delays ~6k cycles so its h1/final
    // phases overlap the 1st CTA's mainloop instead of colliding.
    if (blockIdx.x >= 148) {
        long long s0 = clock64();
        while (clock64() - s0 < 6000) {}
    }

    // warp grid: s = wid&1 (stream); ng = wid>>1 (0..3, n-cols [32ng, 32ng+32))
    const int s  = wid & 1;
    const int ng = wid >> 1;

    float*    pA  = reinterpret_cast<float*>(sm + PA_OFF);
    float4*   pB  = reinterpret_cast<float4*>(sm + PB_OFF);
    uint32_t* w1w = reinterpret_cast<uint32_t*>(sm + W1_OFF);
    float2*   XS  = reinterpret_cast<float2*>(sm + XS_OFF);

    // ---- one-time: pack layer-1 weights into SMEM (fp16x2, lane-major) ----
    if (tid < 128) {
        const int s_ = tid >> 6, g_ = (tid >> 5) & 1, l_ = tid & 31;
        const int k0 = g_ * 64 + 2 * l_;
        const float* w1s_ = s_ ? w1b : w1a;
        const float* b1s_ = s_ ? b1b : b1a;
        const int W = ((s_ * 2 + g_) * 3) * 32 + l_;
        w1w[W]      = pack_f16(w1s_[2 * k0],     w1s_[2 * k0 + 2]);
        w1w[W + 32] = pack_f16(w1s_[2 * k0 + 1], w1s_[2 * k0 + 3]);
        w1w[W + 64] = pack_f16(b1s_[k0],         b1s_[k0 + 1]);
    }

    const float* w2s = s ? w2b : w2a;

    // ---- persistent B fragments (fp16): n = 32ng + 8j + quad, j in 0..3 ----
    uint32_t Bf[4][8][2];
    #pragma unroll
    for (int j = 0; j < 4; ++j) {
        const int n = 32 * ng + 8 * j + quad;
        #pragma unroll
        for (int kk = 0; kk < 8; ++kk) {
            const int k0 = 16 * kk + 2 * qlid;
            float2 lo = *reinterpret_cast<const float2*>(w2s + n * 128 + k0);
            float2 hi = *reinterpret_cast<const float2*>(w2s + n * 128 + k0 + 8);
            Bf[j][kk][0] = pack_f16(lo.x, lo.y);
            Bf[j][kk][1] = pack_f16(hi.x, hi.y);
        }
    }

    // ---- layer-2 bias for this thread's D cols (n = 32ng + 8j + 2qlid + {0,1}) ----
    const float* b2s = s ? b2b : b2a;
    __half2 bias2[4];
    #pragma unroll
    for (int j = 0; j < 4; ++j) {
        const int n = 32 * ng + 8 * j + 2 * qlid;
        bias2[j] = __floats2half2_rn(b2s[n], b2s[n + 1]);
    }

    // ---- w3 B-fragments for the 2 layer-3 reduction mmas (k-slice p: 16 cols) ----
    uint32_t wf3[2][2];
    #pragma unroll
    for (int p = 0; p < 2; ++p) {
        float v0a = 0.f, v0b = 0.f, v1a = 0.f, v1b = 0.f;
        const int kg0 = 32 * ng + 16 * p + 2 * qlid;
        if (s == 0) {
            if (quad == 0) {
                v0a = w3a[kg0];     v0b = w3a[kg0 + 1];
                v1a = w3a[kg0 + 8]; v1b = w3a[kg0 + 9];
            }
        } else {
            if (quad < 3) {
                const float* w3r = w3b + quad * 128;
                v0a = w3r[kg0];     v0b = w3r[kg0 + 1];
                v1a = w3r[kg0 + 8]; v1b = w3r[kg0 + 9];
            }
        }
        wf3[p][0] = pack_f16(v0a, v0b);
        wf3[p][1] = pack_f16(v1a, v1b);
    }

    const float s_b3a = b3a[0];
    const float s_b3b0 = b3b[0], s_b3b1 = b3b[1], s_b3b2 = b3b[2];

    // ldmatrix per-lane source address (m8n8.x4 over 16 rows x 16 cols fp16)
    const uint32_t lrow  = (uint32_t)((lane & 7) + ((lane >> 3) & 1) * 8);
    const uint32_t lcolb = (uint32_t)(((lane >> 4) & 1) * 16);
    const uint32_t aS = smb + (s ? H1B_OFF : H1A_OFF) + lrow * H1_STRIDE + lcolb;

    const int ntiles = Bn >> 7;
    const float2* x2 = reinterpret_cast<const float2*>(x);
    const __half2 z2 = __floats2half2_rn(0.f, 0.f);

    // ---- x prefetch mapping: thread -> (stream = tid>>7, row = tid&127) ----
    const float2* xsrc = x2 + (tid >> 7) * Bn;
    const int pf_row = tid & 127;

    // prologue: stage x for the first tile
    {
        float2 xv = xsrc[blockIdx.x * 128 + pf_row];
        XS[tid] = xv;     // XS index = stream*128 + row == tid
    }
    __syncthreads();   // w1w + first stage visible

    for (int t = blockIdx.x; t < ntiles; t += gridDim.x) {
        // ---- layer 1: h1 = relu(W1 x + b1) -> fp16 SMEM (warp w: rows 16w..16w+15) ----
        {
            __half2 pw[2][2][3];   // short-lived: loaded from smem each tile
            #pragma unroll
            for (int ss = 0; ss < 2; ++ss)
                #pragma unroll
                for (int g = 0; g < 2; ++g)
                    #pragma unroll
                    for (int wh = 0; wh < 3; ++wh) {
                        uint32_t wv = w1w[((ss * 2 + g) * 3 + wh) * 32 + lane];
                        pw[ss][g][wh] = *reinterpret_cast<__half2*>(&wv);
                    }
            #pragma unroll 4
            for (int r = 0; r < 16; ++r) {
                const int row = wid * 16 + r;
                const float2 xa = XS[row];          // broadcast LDS
                const float2 xb = XS[128 + row];    // broadcast LDS
                const __half2 xax = __half2half2(__float2half(xa.x));
                const __half2 xay = __half2half2(__float2half(xa.y));
                const __half2 xbx = __half2half2(__float2half(xb.x));
                const __half2 xby = __half2half2(__float2half(xb.y));
                char* rowa = sm + H1A_OFF + row * H1_STRIDE;
                char* rowb = sm + H1B_OFF + row * H1_STRIDE;
                #pragma unroll
                for (int g = 0; g < 2; ++g) {
                    __half2 ha = __hmax2(
                        __hfma2(xax, pw[0][g][0], __hfma2(xay, pw[0][g][1], pw[0][g][2])), z2);
                    __half2 hb = __hmax2(
                        __hfma2(xbx, pw[1][g][0], __hfma2(xby, pw[1][g][1], pw[1][g][2])), z2);
                    *reinterpret_cast<uint32_t*>(rowa + 128 * g + 4 * lane) =
                        *reinterpret_cast<uint32_t*>(&ha);
                    *reinterpret_cast<uint32_t*>(rowb + 128 * g + 4 * lane) =
                        *reinterpret_cast<uint32_t*>(&hb);
                }
            }
        }
        __syncthreads();

        // ---- prefetch next tile's x into registers (latency hidden by mainloop) ----
        const int tn = t + gridDim.x;
        float2 nxv = xsrc[(tn < ntiles ? tn : blockIdx.x) * 128 + pf_row];

        // ---- layer 2: 8 m-tiles x 32 n-cols per warp (1 ldsm feeds 4 HMMA) ----
        #pragma unroll
        for (int i = 0; i < 8; ++i) {
            const uint32_t ibase = aS + (uint32_t)(i * 16 * H1_STRIDE);

            uint32_t c[4][2];
            #pragma unroll
            for (int j = 0; j < 4; ++j) { c[j][0] = 0u; c[j][1] = 0u; }

            #pragma unroll
            for (int kk = 0; kk < 8; ++kk) {
                uint32_t af[4];
                ldsm_x4(af, ibase + 32u * kk);
                #pragma unroll
                for (int j = 0; j < 4; ++j)
                    mma16816_f16(c[j], af, Bf[j][kk][0], Bf[j][kk][1]);
            }

            // ---- epilogue: bias+relu in half2, layer-3 dot via 2 reduction HMMA ----
            float d[4] = {0.f, 0.f, 0.f, 0.f};
            #pragma unroll
            for (int p = 0; p < 2; ++p) {
                uint32_t h2f[4];
                h2f[0] = h2_bias_relu(c[2 * p][0],     bias2[2 * p],     z2);
                h2f[1] = h2_bias_relu(c[2 * p][1],     bias2[2 * p],     z2);
                h2f[2] = h2_bias_relu(c[2 * p + 1][0], bias2[2 * p + 1], z2);
                h2f[3] = h2_bias_relu(c[2 * p + 1][1], bias2[2 * p + 1], z2);
                mma16816_f32(d, h2f, wf3[p][0], wf3[p][1]);
            }
            // d[0],d[1] = row quad,   cols {2qlid, 2qlid+1}
            // d[2],d[3] = row quad+8, cols {2qlid, 2qlid+1}

            if (s == 0) {
                if (qlid == 0) {
                    pA[ng * 128 + 16 * i + quad]     = d[0];
                    pA[ng * 128 + 16 * i + quad + 8] = d[2];
                }
            } else {
                if (qlid < 2) {
                    float* dst0 = reinterpret_cast<float*>(&pB[ng * 128 + 16 * i + quad]) + 2 * qlid;
                    float* dst1 = reinterpret_cast<float*>(&pB[ng * 128 + 16 * i + quad + 8]) + 2 * qlid;
                    *reinterpret_cast<float2*>(dst0) = make_float2(d[0], d[1]);
                    *reinterpret_cast<float2*>(dst1) = make_float2(d[2], d[3]);
                }
            }
        }

        // stage next tile's x (current tile's stage consumed before sync1)
        XS[tid] = nxv;
        __syncthreads();

        // ---- final: combine 4 n-group partials per stream, softmax, store ----
        if (tid < 128) {
            const int row = tid;
            float oa = s_b3a;
            float o0 = s_b3b0, o1 = s_b3b1, o2 = s_b3b2;
            #pragma unroll
            for (int g = 0; g < 4; ++g) {
                oa += pA[g * 128 + row];
                const float4 qb = pB[g * 128 + row];
                o0 += qb.x; o1 += qb.y; o2 += qb.z;
            }
            const float t0 = oa * o0, t1 = oa * o1, t2 = oa * o2;
            const float mx = fmaxf(t0, fmaxf(t1, t2));
            const float e0 = expf(t0 - mx), e1 = expf(t1 - mx), e2 = expf(t2 - mx);
            const float inv = 1.f / (e0 + e1 + e2);
            const int rg = t * 128 + row;
            out[rg * 3 + 0] = e0 * inv;
            out[rg * 3 + 1] = e1 * inv;
            out[rg * 3 + 2] = e2 * inv;
        }
        // next-tile pA/pB writes are separated from these reads by the
        // h1 __syncthreads at the top of the next iteration.
    }
}

extern "C" void kernel_launch(void* const* d_in, const int* in_sizes, int n_in,
                              void* d_out, int out_size) {
    const float* x   = (const float*)d_in[0];
    const float* w1a = (const float*)d_in[1];
    const float* w1b = (const float*)d_in[2];
    const float* b1a = (const float*)d_in[3];
    const float* b1b = (const float*)d_in[4];
    const float* w2a = (const float*)d_in[5];
    const float* w2b = (const float*)d_in[6];
    const float* b2a = (const float*)d_in[7];
    const float* b2b = (const float*)d_in[8];
    const float* w3a = (const float*)d_in[9];
    const float* w3b = (const float*)d_in[10];
    const float* b3a = (const float*)d_in[11];
    const float* b3b = (const float*)d_in[12];
    float* out = (float*)d_out;

    int Bn = in_sizes[0] / 4;   // x is (2, B, 2) fp32

    cudaFuncSetAttribute(KroneNet_59485297049802_kernel,
                         cudaFuncAttributeMaxDynamicSharedMemorySize, SMEM_TOTAL);
    KroneNet_59485297049802_kernel<<<GRID, TPB, SMEM_TOTAL>>>(
        x, w1a, w1b, b1a, b1b, w2a, w2b, b2a, b2b, w3a, w3b, b3a, b3b, out, Bn);
}